// round 1
// baseline (speedup 1.0000x reference)
#include <cuda_runtime.h>
#include <cstddef>

#define NMAX 100000
#define EMAX 1600000
#define FDIM 128
#define ALPHA_C 0.1f
#define LEAKY_C 0.2f

// ---------------- static scratch (no allocs allowed) ----------------
__device__ unsigned g_m[NMAX];            // row max (flip-encoded)
__device__ float    g_s[NMAX];            // row exp-sum
__device__ float    g_rowsum[NMAX];       // rowsum of adj .* P
__device__ int      g_count[NMAX];        // row degree
__device__ int      g_wr[NMAX];           // row write cursor
__device__ int      g_off[NMAX + 1];      // CSR offsets
__device__ int      g_bsum[1024];         // scan block sums
__device__ float    g_feat1[NMAX];
__device__ float    g_feat2[NMAX];
__device__ float    g_ev[EMAX];           // edge value: e then exp(e-m)
__device__ int      g_col_s[EMAX];        // CSR cols
__device__ float    g_u_s[EMAX];          // CSR softmax values
__device__ float    g_updA[(size_t)NMAX * FDIM];
__device__ float    g_updB[(size_t)NMAX * FDIM];

// ---------------- helpers ----------------
__device__ __forceinline__ unsigned fflip(float f) {
    unsigned u = __float_as_uint(f);
    return (u & 0x80000000u) ? ~u : (u | 0x80000000u);
}
__device__ __forceinline__ float funflip(unsigned u) {
    return __uint_as_float((u & 0x80000000u) ? (u ^ 0x80000000u) : ~u);
}

// ---------------- kernels ----------------
__global__ void k_init(int n) {
    int i = blockIdx.x * blockDim.x + threadIdx.x;
    if (i >= n) return;
    g_m[i] = 0u;          // flip(-inf)=0x007fffff > 0, so 0 is identity for max
    g_s[i] = 0.f;
    g_rowsum[i] = 0.f;
    g_count[i] = 0;
    g_wr[i] = 0;
}

// feat1/feat2: one warp per node, float4 lanes, warp reduce
__global__ void k_feats(const float* __restrict__ x, const float* __restrict__ a, int n) {
    int gw = (blockIdx.x * blockDim.x + threadIdx.x) >> 5;
    int lane = threadIdx.x & 31;
    if (gw >= n) return;
    float4 v  = __ldg((const float4*)(x + (size_t)gw * FDIM) + lane);
    float4 a1 = __ldg((const float4*)a + lane);
    float4 a2 = __ldg((const float4*)(a + FDIM) + lane);
    float d1 = v.x * a1.x + v.y * a1.y + v.z * a1.z + v.w * a1.w;
    float d2 = v.x * a2.x + v.y * a2.y + v.z * a2.z + v.w * a2.w;
    #pragma unroll
    for (int o = 16; o; o >>= 1) {
        d1 += __shfl_down_sync(0xffffffffu, d1, o);
        d2 += __shfl_down_sync(0xffffffffu, d2, o);
    }
    if (lane == 0) { g_feat1[gw] = d1; g_feat2[gw] = d2; }
}

// edge pass 1: leaky-relu value, row max, row degree
__global__ void k_edge1(const int* __restrict__ row, const int* __restrict__ col, int e) {
    int j = blockIdx.x * blockDim.x + threadIdx.x;
    if (j >= e) return;
    int r = row[j];
    float ev = g_feat1[r] + g_feat2[col[j]];
    ev = (ev >= 0.f) ? ev : LEAKY_C * ev;
    g_ev[j] = ev;
    atomicMax(&g_m[r], fflip(ev));
    atomicAdd(&g_count[r], 1);
}

// edge pass 2: exp(e - max), row sum
__global__ void k_edge2(const int* __restrict__ row, int e) {
    int j = blockIdx.x * blockDim.x + threadIdx.x;
    if (j >= e) return;
    int r = row[j];
    float ex = __expf(g_ev[j] - funflip(g_m[r]));
    g_ev[j] = ex;
    atomicAdd(&g_s[r], ex);
}

// scan 1: per-1024-block exclusive scan of degrees
__global__ void k_scan1(int n) {
    __shared__ int sh[1024];
    int i = blockIdx.x * 1024 + threadIdx.x;
    int v = (i < n) ? g_count[i] : 0;
    sh[threadIdx.x] = v;
    __syncthreads();
    #pragma unroll
    for (int o = 1; o < 1024; o <<= 1) {
        int t = (threadIdx.x >= o) ? sh[threadIdx.x - o] : 0;
        __syncthreads();
        sh[threadIdx.x] += t;
        __syncthreads();
    }
    if (i < n) g_off[i] = sh[threadIdx.x] - v;   // exclusive
    if (threadIdx.x == 1023) g_bsum[blockIdx.x] = sh[1023];
}

// scan 2: serial scan of block sums (~98 values), set g_off[n]
__global__ void k_scan2(int nb, int n) {
    int run = 0;
    for (int b = 0; b < nb; b++) { int t = g_bsum[b]; g_bsum[b] = run; run += t; }
    g_off[n] = run;
}

// scan 3: add block offsets
__global__ void k_scan3(int n) {
    int i = blockIdx.x * 1024 + threadIdx.x;
    if (i < n) g_off[i] += g_bsum[blockIdx.x];
}

// edge pass 3: finalize softmax, rowsum, scatter into CSR
__global__ void k_scatter(const int* __restrict__ row, const int* __restrict__ col,
                          const float* __restrict__ adj, int e) {
    int j = blockIdx.x * blockDim.x + threadIdx.x;
    if (j >= e) return;
    int r = row[j];
    float u = g_ev[j] / g_s[r];
    atomicAdd(&g_rowsum[r], 0.5f * adj[j] * u);
    int pos = g_off[r] + atomicAdd(&g_wr[r], 1);
    g_col_s[pos] = col[j];
    g_u_s[pos] = u;
}

// fused SpMM + lifting + feat_prime accumulation. One block (128 thr) per row.
__global__ void k_spmm(const float* __restrict__ x, float* __restrict__ fp,
                       const float* __restrict__ cheb, int step, int n) {
    int r = blockIdx.x;
    if (r >= n) return;
    int tid = threadIdx.x;

    const float* in_upd = (step == 0) ? x : ((step == 1) ? g_updA : g_updB);
    float* out_upd = (step == 0) ? g_updA : g_updB;
    const float* fp_in = (step == 0) ? x : fp;

    __shared__ int   sc[128];
    __shared__ float su[128];

    int beg = g_off[r], end = g_off[r + 1];
    float acc = 0.f;
    for (int j0 = beg; j0 < end; j0 += 128) {
        int chunk = min(128, end - j0);
        __syncthreads();
        if (tid < chunk) { sc[tid] = g_col_s[j0 + tid]; su[tid] = g_u_s[j0 + tid]; }
        __syncthreads();
        for (int k = 0; k < chunk; k++)
            acc += su[k] * __ldg(&in_upd[(size_t)sc[k] * FDIM + tid]);
    }

    size_t idx = (size_t)r * FDIM + tid;
    if (step < 2) out_upd[idx] = acc;      // dead on last step

    float rs = g_rowsum[r];
    if (step >= 1) rs *= 1.f / (1.f + __expf(-__ldg(&cheb[0])));
    if (step >= 2) rs *= 1.f / (1.f + __expf(-__ldg(&cheb[1])));
    // fuse = ALPHA*u + (1-ALPHA)*u*(1-rs) = u*(1 - 0.9*rs)
    float fuse = acc * (1.f - 0.9f * rs);
    fp[idx] = ALPHA_C * fp_in[idx] + 0.9f * fuse;
}

// ---------------- launch ----------------
extern "C" void kernel_launch(void* const* d_in, const int* in_sizes, int n_in,
                              void* d_out, int out_size) {
    const float* x    = (const float*)d_in[0];
    // d_in[1] = h0 (unused), d_in[3] = temp (unused)
    const float* a    = (const float*)d_in[2];
    const float* cheb = (const float*)d_in[4];
    const float* adj  = (const float*)d_in[5];
    const int*   row  = (const int*)d_in[6];
    const int*   col  = (const int*)d_in[7];
    float* out = (float*)d_out;

    int n = in_sizes[0] / FDIM;
    int e = in_sizes[5];

    k_init<<<(n + 255) / 256, 256>>>(n);
    k_feats<<<((size_t)n * 32 + 255) / 256, 256>>>(x, a, n);
    k_edge1<<<(e + 255) / 256, 256>>>(row, col, e);
    k_edge2<<<(e + 255) / 256, 256>>>(row, e);

    int nb = (n + 1023) / 1024;
    k_scan1<<<nb, 1024>>>(n);
    k_scan2<<<1, 1>>>(nb, n);
    k_scan3<<<nb, 1024>>>(n);

    k_scatter<<<(e + 255) / 256, 256>>>(row, col, adj, e);

    for (int step = 0; step < 3; step++)
        k_spmm<<<n, FDIM>>>(x, out, cheb, step, n);
}

// round 2
// speedup vs baseline: 1.5960x; 1.5960x over previous
#include <cuda_runtime.h>
#include <cstddef>

#define NMAX 100000
#define EMAX 1600000
#define FDIM 128
#define ALPHA_C 0.1f
#define LEAKY_C 0.2f

// ---------------- static scratch (no allocs allowed) ----------------
__device__ unsigned g_m[NMAX];            // row max (flip-encoded)
__device__ float    g_s[NMAX];            // row exp-sum
__device__ float    g_rowsum[NMAX];       // rowsum of adj .* P
__device__ int      g_count[NMAX];        // row degree
__device__ int      g_wr[NMAX];           // row write cursor
__device__ int      g_off[NMAX + 1];      // CSR offsets
__device__ int      g_bsum[1024];         // scan block sums
__device__ float    g_feat1[NMAX];
__device__ float    g_feat2[NMAX];
__device__ float    g_ev[EMAX];           // edge value: e then exp(e-m)
__device__ int      g_col_s[EMAX];        // CSR cols
__device__ float    g_u_s[EMAX];          // CSR softmax values
__device__ float    g_updA[(size_t)NMAX * FDIM];
__device__ float    g_updB[(size_t)NMAX * FDIM];

// ---------------- helpers ----------------
__device__ __forceinline__ unsigned fflip(float f) {
    unsigned u = __float_as_uint(f);
    return (u & 0x80000000u) ? ~u : (u | 0x80000000u);
}
__device__ __forceinline__ float funflip(unsigned u) {
    return __uint_as_float((u & 0x80000000u) ? (u ^ 0x80000000u) : ~u);
}

// ---------------- kernels ----------------
__global__ void k_init(int n) {
    int i = blockIdx.x * blockDim.x + threadIdx.x;
    if (i >= n) return;
    g_m[i] = 0u;
    g_s[i] = 0.f;
    g_rowsum[i] = 0.f;
    g_count[i] = 0;
    g_wr[i] = 0;
}

// feat1/feat2: one warp per node, float4 lanes, warp reduce
__global__ void k_feats(const float* __restrict__ x, const float* __restrict__ a, int n) {
    int gw = (blockIdx.x * blockDim.x + threadIdx.x) >> 5;
    int lane = threadIdx.x & 31;
    if (gw >= n) return;
    float4 v  = __ldg((const float4*)(x + (size_t)gw * FDIM) + lane);
    float4 a1 = __ldg((const float4*)a + lane);
    float4 a2 = __ldg((const float4*)(a + FDIM) + lane);
    float d1 = v.x * a1.x + v.y * a1.y + v.z * a1.z + v.w * a1.w;
    float d2 = v.x * a2.x + v.y * a2.y + v.z * a2.z + v.w * a2.w;
    #pragma unroll
    for (int o = 16; o; o >>= 1) {
        d1 += __shfl_down_sync(0xffffffffu, d1, o);
        d2 += __shfl_down_sync(0xffffffffu, d2, o);
    }
    if (lane == 0) { g_feat1[gw] = d1; g_feat2[gw] = d2; }
}

// edge pass 1: leaky-relu value, row max, row degree
__global__ void k_edge1(const int* __restrict__ row, const int* __restrict__ col, int e) {
    int j = blockIdx.x * blockDim.x + threadIdx.x;
    if (j >= e) return;
    int r = row[j];
    float ev = g_feat1[r] + g_feat2[col[j]];
    ev = (ev >= 0.f) ? ev : LEAKY_C * ev;
    g_ev[j] = ev;
    atomicMax(&g_m[r], fflip(ev));
    atomicAdd(&g_count[r], 1);
}

// edge pass 2: exp(e - max), row sum
__global__ void k_edge2(const int* __restrict__ row, int e) {
    int j = blockIdx.x * blockDim.x + threadIdx.x;
    if (j >= e) return;
    int r = row[j];
    float ex = __expf(g_ev[j] - funflip(g_m[r]));
    g_ev[j] = ex;
    atomicAdd(&g_s[r], ex);
}

// scan 1: per-1024-block exclusive scan of degrees
__global__ void k_scan1(int n) {
    __shared__ int sh[1024];
    int i = blockIdx.x * 1024 + threadIdx.x;
    int v = (i < n) ? g_count[i] : 0;
    sh[threadIdx.x] = v;
    __syncthreads();
    #pragma unroll
    for (int o = 1; o < 1024; o <<= 1) {
        int t = (threadIdx.x >= o) ? sh[threadIdx.x - o] : 0;
        __syncthreads();
        sh[threadIdx.x] += t;
        __syncthreads();
    }
    if (i < n) g_off[i] = sh[threadIdx.x] - v;
    if (threadIdx.x == 1023) g_bsum[blockIdx.x] = sh[1023];
}

__global__ void k_scan2(int nb, int n) {
    int run = 0;
    for (int b = 0; b < nb; b++) { int t = g_bsum[b]; g_bsum[b] = run; run += t; }
    g_off[n] = run;
}

__global__ void k_scan3(int n) {
    int i = blockIdx.x * 1024 + threadIdx.x;
    if (i < n) g_off[i] += g_bsum[blockIdx.x];
}

// edge pass 3: finalize softmax, rowsum, scatter into CSR
__global__ void k_scatter(const int* __restrict__ row, const int* __restrict__ col,
                          const float* __restrict__ adj, int e) {
    int j = blockIdx.x * blockDim.x + threadIdx.x;
    if (j >= e) return;
    int r = row[j];
    float u = g_ev[j] / g_s[r];
    atomicAdd(&g_rowsum[r], 0.5f * adj[j] * u);
    int pos = g_off[r] + atomicAdd(&g_wr[r], 1);
    g_col_s[pos] = col[j];
    g_u_s[pos] = u;
}

// fused SpMM + lifting + feat_prime. One WARP per row, float4 per lane.
__global__ void __launch_bounds__(256) k_spmm(const float* __restrict__ x,
                                              float* __restrict__ fp,
                                              const float* __restrict__ cheb,
                                              int step, int n) {
    int warp = (blockIdx.x * blockDim.x + threadIdx.x) >> 5;
    int lane = threadIdx.x & 31;
    if (warp >= n) return;
    int r = warp;

    const float* in_upd = (step == 0) ? x : ((step == 1) ? g_updA : g_updB);
    float*       out_upd = (step == 0) ? g_updA : g_updB;
    const float* fp_in  = (step == 0) ? x : fp;

    int beg = __ldg(&g_off[r]), end = __ldg(&g_off[r + 1]);

    float4 acc = make_float4(0.f, 0.f, 0.f, 0.f);

    for (int j0 = beg; j0 < end; j0 += 32) {
        int k = j0 + lane;
        int   c = 0;
        float u = 0.f;
        if (k < end) { c = __ldg(&g_col_s[k]); u = __ldg(&g_u_s[k]); }
        int m = min(32, end - j0);
        #pragma unroll 4
        for (int t = 0; t < m; t++) {
            int   cc = __shfl_sync(0xffffffffu, c, t);
            float uu = __shfl_sync(0xffffffffu, u, t);
            float4 v = __ldg((const float4*)(in_upd + (size_t)cc * FDIM) + lane);
            acc.x += uu * v.x;
            acc.y += uu * v.y;
            acc.z += uu * v.z;
            acc.w += uu * v.w;
        }
    }

    size_t v4idx = (size_t)r * (FDIM / 4) + lane;
    if (step < 2) ((float4*)out_upd)[v4idx] = acc;   // dead on last step

    float rs = __ldg(&g_rowsum[r]);
    if (step >= 1) rs *= 1.f / (1.f + __expf(-__ldg(&cheb[0])));
    if (step >= 2) rs *= 1.f / (1.f + __expf(-__ldg(&cheb[1])));
    float scale = 0.9f * (1.f - 0.9f * rs);          // 0.9 * fuse-factor

    float4 xin = __ldg((const float4*)fp_in + v4idx);
    float4 o;
    o.x = ALPHA_C * xin.x + scale * acc.x;
    o.y = ALPHA_C * xin.y + scale * acc.y;
    o.z = ALPHA_C * xin.z + scale * acc.z;
    o.w = ALPHA_C * xin.w + scale * acc.w;
    ((float4*)fp)[v4idx] = o;
}

// ---------------- launch ----------------
extern "C" void kernel_launch(void* const* d_in, const int* in_sizes, int n_in,
                              void* d_out, int out_size) {
    const float* x    = (const float*)d_in[0];
    const float* a    = (const float*)d_in[2];
    const float* cheb = (const float*)d_in[4];
    const float* adj  = (const float*)d_in[5];
    const int*   row  = (const int*)d_in[6];
    const int*   col  = (const int*)d_in[7];
    float* out = (float*)d_out;

    int n = in_sizes[0] / FDIM;
    int e = in_sizes[5];

    k_init<<<(n + 255) / 256, 256>>>(n);
    k_feats<<<((size_t)n * 32 + 255) / 256, 256>>>(x, a, n);
    k_edge1<<<(e + 255) / 256, 256>>>(row, col, e);
    k_edge2<<<(e + 255) / 256, 256>>>(row, e);

    int nb = (n + 1023) / 1024;
    k_scan1<<<nb, 1024>>>(n);
    k_scan2<<<1, 1>>>(nb, n);
    k_scan3<<<nb, 1024>>>(n);

    k_scatter<<<(e + 255) / 256, 256>>>(row, col, adj, e);

    // 8 warps (8 rows) per 256-thread block
    int spmm_blocks = (n + 7) / 8;
    for (int step = 0; step < 3; step++)
        k_spmm<<<spmm_blocks, 256>>>(x, out, cheb, step, n);
}

// round 3
// speedup vs baseline: 1.7904x; 1.1218x over previous
#include <cuda_runtime.h>
#include <cstddef>

#define NMAX 100000
#define EMAX 1600000
#define FDIM 128
#define ALPHA_C 0.1f

// ---------------- static scratch (no allocs allowed) ----------------
__device__ float    g_s[NMAX];            // row exp-sum (unnormalized)
__device__ float    g_rowsum[NMAX];       // rowsum of adj .* P (unnormalized)
__device__ int      g_count[NMAX];        // row degree
__device__ int      g_wr[NMAX];           // row write cursor
__device__ int      g_off[NMAX + 1];      // CSR offsets
__device__ int      g_bsum[1024];         // scan block sums
__device__ float    g_feat1[NMAX];
__device__ float    g_feat2[NMAX];
__device__ float    g_ev[EMAX];           // exp(leaky(e)) per edge (COO order)
__device__ int      g_col_s[EMAX];        // CSR cols
__device__ float    g_u_s[EMAX];          // CSR unnormalized softmax values
__device__ float    g_updA[(size_t)NMAX * FDIM];
__device__ float    g_updB[(size_t)NMAX * FDIM];

// ---------------- kernels ----------------
__global__ void k_init(int n) {
    int i = blockIdx.x * blockDim.x + threadIdx.x;
    if (i >= n) return;
    g_s[i] = 0.f;
    g_rowsum[i] = 0.f;
    g_count[i] = 0;
    g_wr[i] = 0;
}

// feat1/feat2: one warp per node, float4 lanes, warp reduce
__global__ void k_feats(const float* __restrict__ x, const float* __restrict__ a, int n) {
    int gw = (blockIdx.x * blockDim.x + threadIdx.x) >> 5;
    int lane = threadIdx.x & 31;
    if (gw >= n) return;
    float4 v  = __ldg((const float4*)(x + (size_t)gw * FDIM) + lane);
    float4 a1 = __ldg((const float4*)a + lane);
    float4 a2 = __ldg((const float4*)(a + FDIM) + lane);
    float d1 = v.x * a1.x + v.y * a1.y + v.z * a1.z + v.w * a1.w;
    float d2 = v.x * a2.x + v.y * a2.y + v.z * a2.z + v.w * a2.w;
    #pragma unroll
    for (int o = 16; o; o >>= 1) {
        d1 += __shfl_down_sync(0xffffffffu, d1, o);
        d2 += __shfl_down_sync(0xffffffffu, d2, o);
    }
    if (lane == 0) { g_feat1[gw] = d1; g_feat2[gw] = d2; }
}

// single edge pass: exp(leaky(e)) (no max-shift), row sum, row degree
__global__ void k_edge1(const int* __restrict__ row, const int* __restrict__ col, int e) {
    int j = blockIdx.x * blockDim.x + threadIdx.x;
    if (j >= e) return;
    int r = row[j];
    float ev = __ldg(&g_feat1[r]) + __ldg(&g_feat2[col[j]]);
    ev = (ev >= 0.f) ? ev : 0.2f * ev;
    float ex = __expf(ev);
    g_ev[j] = ex;
    atomicAdd(&g_s[r], ex);
    atomicAdd(&g_count[r], 1);
}

// scan 1: per-1024-block exclusive scan of degrees
__global__ void k_scan1(int n) {
    __shared__ int sh[1024];
    int i = blockIdx.x * 1024 + threadIdx.x;
    int v = (i < n) ? g_count[i] : 0;
    sh[threadIdx.x] = v;
    __syncthreads();
    #pragma unroll
    for (int o = 1; o < 1024; o <<= 1) {
        int t = (threadIdx.x >= o) ? sh[threadIdx.x - o] : 0;
        __syncthreads();
        sh[threadIdx.x] += t;
        __syncthreads();
    }
    if (i < n) g_off[i] = sh[threadIdx.x] - v;
    if (threadIdx.x == 1023) g_bsum[blockIdx.x] = sh[1023];
}

__global__ void k_scan2(int nb, int n) {
    int run = 0;
    for (int b = 0; b < nb; b++) { int t = g_bsum[b]; g_bsum[b] = run; run += t; }
    g_off[n] = run;
}

__global__ void k_scan3(int n) {
    int i = blockIdx.x * 1024 + threadIdx.x;
    if (i < n) g_off[i] += g_bsum[blockIdx.x];
}

// edge pass 2: scatter unnormalized values into CSR, accumulate rowsum
__global__ void k_scatter(const int* __restrict__ row, const int* __restrict__ col,
                          const float* __restrict__ adj, int e) {
    int j = blockIdx.x * blockDim.x + threadIdx.x;
    if (j >= e) return;
    int r = row[j];
    float ex = g_ev[j];
    atomicAdd(&g_rowsum[r], 0.5f * adj[j] * ex);      // unnormalized
    int pos = g_off[r] + atomicAdd(&g_wr[r], 1);
    g_col_s[pos] = col[j];
    g_u_s[pos] = ex;                                   // unnormalized
}

// fused SpMM. One WARP per row, float4 per lane.
// step 0: updA = (U x)            (normalized at write)
// step 1: upB  = (U updA)
// step 2: acc3 = (U updB); out = 0.001 x + 0.009(1-0.9 rs0) updA
//                              + 0.09(1-0.9 rs1) updB + 0.9(1-0.9 rs2) acc3
__global__ void __launch_bounds__(256) k_spmm(const float* __restrict__ x,
                                              float* __restrict__ out,
                                              const float* __restrict__ cheb,
                                              int step, int n) {
    int warp = (blockIdx.x * blockDim.x + threadIdx.x) >> 5;
    int lane = threadIdx.x & 31;
    if (warp >= n) return;
    int r = warp;

    const float* in_upd = (step == 0) ? x : ((step == 1) ? g_updA : g_updB);

    int beg = __ldg(&g_off[r]), end = __ldg(&g_off[r + 1]);
    float s = __ldg(&g_s[r]);
    float inv_s = (s > 0.f) ? 1.f / s : 0.f;

    float4 acc = make_float4(0.f, 0.f, 0.f, 0.f);

    for (int j0 = beg; j0 < end; j0 += 32) {
        int k = j0 + lane;
        int   c = 0;
        float u = 0.f;
        if (k < end) { c = __ldg(&g_col_s[k]); u = __ldg(&g_u_s[k]); }
        int m = min(32, end - j0);
        #pragma unroll 4
        for (int t = 0; t < m; t++) {
            int   cc = __shfl_sync(0xffffffffu, c, t);
            float uu = __shfl_sync(0xffffffffu, u, t);
            float4 v = __ldg((const float4*)(in_upd + (size_t)cc * FDIM) + lane);
            acc.x += uu * v.x;
            acc.y += uu * v.y;
            acc.z += uu * v.z;
            acc.w += uu * v.w;
        }
    }
    acc.x *= inv_s; acc.y *= inv_s; acc.z *= inv_s; acc.w *= inv_s;

    size_t v4idx = (size_t)r * (FDIM / 4) + lane;
    if (step == 0) {
        ((float4*)g_updA)[v4idx] = acc;
    } else if (step == 1) {
        ((float4*)g_updB)[v4idx] = acc;
    } else {
        float rs0 = __ldg(&g_rowsum[r]) * inv_s;
        float c0 = 1.f / (1.f + __expf(-__ldg(&cheb[0])));
        float c1 = 1.f / (1.f + __expf(-__ldg(&cheb[1])));
        float rs1 = rs0 * c0;
        float rs2 = rs1 * c1;
        float w0 = 0.009f * (1.f - 0.9f * rs0);
        float w1 = 0.09f  * (1.f - 0.9f * rs1);
        float w2 = 0.9f   * (1.f - 0.9f * rs2);

        float4 xv = __ldg((const float4*)x + v4idx);
        float4 ua = ((const float4*)g_updA)[v4idx];
        float4 ub = ((const float4*)g_updB)[v4idx];
        float4 o;
        o.x = 0.001f * xv.x + w0 * ua.x + w1 * ub.x + w2 * acc.x;
        o.y = 0.001f * xv.y + w0 * ua.y + w1 * ub.y + w2 * acc.y;
        o.z = 0.001f * xv.z + w0 * ua.z + w1 * ub.z + w2 * acc.z;
        o.w = 0.001f * xv.w + w0 * ua.w + w1 * ub.w + w2 * acc.w;
        ((float4*)out)[v4idx] = o;
    }
}

// ---------------- launch ----------------
extern "C" void kernel_launch(void* const* d_in, const int* in_sizes, int n_in,
                              void* d_out, int out_size) {
    const float* x    = (const float*)d_in[0];
    const float* a    = (const float*)d_in[2];
    const float* cheb = (const float*)d_in[4];
    const float* adj  = (const float*)d_in[5];
    const int*   row  = (const int*)d_in[6];
    const int*   col  = (const int*)d_in[7];
    float* out = (float*)d_out;

    int n = in_sizes[0] / FDIM;
    int e = in_sizes[5];

    k_init<<<(n + 255) / 256, 256>>>(n);
    k_feats<<<((size_t)n * 32 + 255) / 256, 256>>>(x, a, n);
    k_edge1<<<(e + 255) / 256, 256>>>(row, col, e);

    int nb = (n + 1023) / 1024;
    k_scan1<<<nb, 1024>>>(n);
    k_scan2<<<1, 1>>>(nb, n);
    k_scan3<<<nb, 1024>>>(n);

    k_scatter<<<(e + 255) / 256, 256>>>(row, col, adj, e);

    int spmm_blocks = (n + 7) / 8;
    for (int step = 0; step < 3; step++)
        k_spmm<<<spmm_blocks, 256>>>(x, out, cheb, step, n);
}

// round 6
// speedup vs baseline: 1.9653x; 1.0977x over previous
#include <cuda_runtime.h>
#include <cuda_fp16.h>
#include <cstddef>

#define NMAX 100000
#define EMAX 1600000
#define FDIM 128

// ---------------- static scratch (no allocs allowed) ----------------
__device__ float    g_s[NMAX];            // row exp-sum (unnormalized)
__device__ float    g_rowsum[NMAX];       // rowsum of adj .* P (unnormalized)
__device__ int      g_count[NMAX];        // row degree
__device__ int      g_wr[NMAX];           // row write cursor
__device__ int      g_off[NMAX + 1];      // CSR offsets
__device__ int      g_bsum[1024];         // scan block sums
__device__ float    g_feat1[NMAX];
__device__ float    g_feat2[NMAX];
__device__ float    g_ev[EMAX];           // exp(leaky(e)) per edge (COO order)
__device__ int      g_col_s[EMAX];        // CSR cols
__device__ float    g_u_s[EMAX];          // CSR unnormalized softmax values
__device__ __half   g_xh[(size_t)NMAX * FDIM];   // fp16 copy of x
__device__ __half   g_hA[(size_t)NMAX * FDIM];   // fp16 update hop1
__device__ __half   g_hB[(size_t)NMAX * FDIM];   // fp16 update hop2

// ---------------- kernels ----------------
__global__ void k_init(int n) {
    int i = blockIdx.x * blockDim.x + threadIdx.x;
    if (i >= n) return;
    g_s[i] = 0.f;
    g_rowsum[i] = 0.f;
    g_count[i] = 0;
    g_wr[i] = 0;
}

// feat1/feat2 dot products + fused x -> fp16 conversion.
// One warp per node, float4 lanes.
__global__ void k_feats(const float* __restrict__ x, const float* __restrict__ a, int n) {
    int gw = (blockIdx.x * blockDim.x + threadIdx.x) >> 5;
    int lane = threadIdx.x & 31;
    if (gw >= n) return;
    float4 v  = __ldg((const float4*)(x + (size_t)gw * FDIM) + lane);
    float4 a1 = __ldg((const float4*)a + lane);
    float4 a2 = __ldg((const float4*)(a + FDIM) + lane);

    // fp16 copy of this x row (lane owns features [4*lane, 4*lane+4))
    __half2 h0 = __floats2half2_rn(v.x, v.y);
    __half2 h1 = __floats2half2_rn(v.z, v.w);
    uint2 packed;
    packed.x = *(unsigned*)&h0;
    packed.y = *(unsigned*)&h1;
    ((uint2*)g_xh)[(size_t)gw * 32 + lane] = packed;

    float d1 = v.x * a1.x + v.y * a1.y + v.z * a1.z + v.w * a1.w;
    float d2 = v.x * a2.x + v.y * a2.y + v.z * a2.z + v.w * a2.w;
    #pragma unroll
    for (int o = 16; o; o >>= 1) {
        d1 += __shfl_down_sync(0xffffffffu, d1, o);
        d2 += __shfl_down_sync(0xffffffffu, d2, o);
    }
    if (lane == 0) { g_feat1[gw] = d1; g_feat2[gw] = d2; }
}

// single edge pass: exp(leaky(e)) (no max-shift), row sum, row degree
__global__ void k_edge1(const int* __restrict__ row, const int* __restrict__ col, int e) {
    int j = blockIdx.x * blockDim.x + threadIdx.x;
    if (j >= e) return;
    int r = row[j];
    float ev = __ldg(&g_feat1[r]) + __ldg(&g_feat2[col[j]]);
    ev = (ev >= 0.f) ? ev : 0.2f * ev;
    float ex = __expf(ev);
    g_ev[j] = ex;
    atomicAdd(&g_s[r], ex);
    atomicAdd(&g_count[r], 1);
}

// scan 1: per-1024-block exclusive scan of degrees
__global__ void k_scan1(int n) {
    __shared__ int sh[1024];
    int i = blockIdx.x * 1024 + threadIdx.x;
    int v = (i < n) ? g_count[i] : 0;
    sh[threadIdx.x] = v;
    __syncthreads();
    #pragma unroll
    for (int o = 1; o < 1024; o <<= 1) {
        int t = (threadIdx.x >= o) ? sh[threadIdx.x - o] : 0;
        __syncthreads();
        sh[threadIdx.x] += t;
        __syncthreads();
    }
    if (i < n) g_off[i] = sh[threadIdx.x] - v;
    if (threadIdx.x == 1023) g_bsum[blockIdx.x] = sh[1023];
}

__global__ void k_scan2(int nb, int n) {
    int run = 0;
    for (int b = 0; b < nb; b++) { int t = g_bsum[b]; g_bsum[b] = run; run += t; }
    g_off[n] = run;
}

__global__ void k_scan3(int n) {
    int i = blockIdx.x * 1024 + threadIdx.x;
    if (i < n) g_off[i] += g_bsum[blockIdx.x];
}

// edge pass 2: scatter unnormalized values into CSR, accumulate rowsum
__global__ void k_scatter(const int* __restrict__ row, const int* __restrict__ col,
                          const float* __restrict__ adj, int e) {
    int j = blockIdx.x * blockDim.x + threadIdx.x;
    if (j >= e) return;
    int r = row[j];
    float ex = g_ev[j];
    atomicAdd(&g_rowsum[r], 0.5f * adj[j] * ex);
    int pos = g_off[r] + atomicAdd(&g_wr[r], 1);
    g_col_s[pos] = col[j];
    g_u_s[pos] = ex;
}

// fused SpMM, fp16 gather operands, fp32 accumulation.
// One WARP per row; lane owns 4 features (one uint2 = 4 halves per edge).
// step 0: hA = U @ xh       step 1: hB = U @ hA
// step 2: acc = U @ hB; out = 0.001 x + w0*hA + w1*hB + w2*acc   (fp32 out)
__global__ void __launch_bounds__(256) k_spmm(const float* __restrict__ x,
                                              float* __restrict__ out,
                                              const float* __restrict__ cheb,
                                              int step, int n) {
    int warp = (blockIdx.x * blockDim.x + threadIdx.x) >> 5;
    int lane = threadIdx.x & 31;
    if (warp >= n) return;
    int r = warp;

    const uint2* in_upd = (const uint2*)((step == 0) ? g_xh : ((step == 1) ? g_hA : g_hB));

    int beg = __ldg(&g_off[r]), end = __ldg(&g_off[r + 1]);
    float s = __ldg(&g_s[r]);
    float inv_s = (s > 0.f) ? 1.f / s : 0.f;

    float4 acc = make_float4(0.f, 0.f, 0.f, 0.f);

    for (int j0 = beg; j0 < end; j0 += 32) {
        int k = j0 + lane;
        int   c = 0;
        float u = 0.f;
        if (k < end) { c = __ldg(&g_col_s[k]); u = __ldg(&g_u_s[k]); }
        int m = min(32, end - j0);
        #pragma unroll 4
        for (int t = 0; t < m; t++) {
            int   cc = __shfl_sync(0xffffffffu, c, t);
            float uu = __shfl_sync(0xffffffffu, u, t);
            uint2 raw = __ldg(in_upd + (size_t)cc * 32 + lane);
            __half2 h0 = *(__half2*)&raw.x;
            __half2 h1 = *(__half2*)&raw.y;
            float2 f0 = __half22float2(h0);
            float2 f1 = __half22float2(h1);
            acc.x += uu * f0.x;
            acc.y += uu * f0.y;
            acc.z += uu * f1.x;
            acc.w += uu * f1.y;
        }
    }
    acc.x *= inv_s; acc.y *= inv_s; acc.z *= inv_s; acc.w *= inv_s;

    size_t v2idx = (size_t)r * 32 + lane;
    if (step < 2) {
        __half2 h0 = __floats2half2_rn(acc.x, acc.y);
        __half2 h1 = __floats2half2_rn(acc.z, acc.w);
        uint2 packed;
        packed.x = *(unsigned*)&h0;
        packed.y = *(unsigned*)&h1;
        ((uint2*)(step == 0 ? g_hA : g_hB))[v2idx] = packed;
    } else {
        float rs0 = __ldg(&g_rowsum[r]) * inv_s;
        float c0 = 1.f / (1.f + __expf(-__ldg(&cheb[0])));
        float c1 = 1.f / (1.f + __expf(-__ldg(&cheb[1])));
        float rs1 = rs0 * c0;
        float rs2 = rs1 * c1;
        float w0 = 0.009f * (1.f - 0.9f * rs0);
        float w1 = 0.09f  * (1.f - 0.9f * rs1);
        float w2 = 0.9f   * (1.f - 0.9f * rs2);

        size_t v4idx = (size_t)r * (FDIM / 4) + lane;
        float4 xv = __ldg((const float4*)x + v4idx);
        uint2 rawa = ((const uint2*)g_hA)[v2idx];
        uint2 rawb = ((const uint2*)g_hB)[v2idx];
        float2 a0 = __half22float2(*(__half2*)&rawa.x);
        float2 a1 = __half22float2(*(__half2*)&rawa.y);
        float2 b0 = __half22float2(*(__half2*)&rawb.x);
        float2 b1 = __half22float2(*(__half2*)&rawb.y);
        float4 o;
        o.x = 0.001f * xv.x + w0 * a0.x + w1 * b0.x + w2 * acc.x;
        o.y = 0.001f * xv.y + w0 * a0.y + w1 * b0.y + w2 * acc.y;
        o.z = 0.001f * xv.z + w0 * a1.x + w1 * b1.x + w2 * acc.z;
        o.w = 0.001f * xv.w + w0 * a1.y + w1 * b1.y + w2 * acc.w;
        ((float4*)out)[v4idx] = o;
    }
}

// ---------------- launch ----------------
extern "C" void kernel_launch(void* const* d_in, const int* in_sizes, int n_in,
                              void* d_out, int out_size) {
    const float* x    = (const float*)d_in[0];
    const float* a    = (const float*)d_in[2];
    const float* cheb = (const float*)d_in[4];
    const float* adj  = (const float*)d_in[5];
    const int*   row  = (const int*)d_in[6];
    const int*   col  = (const int*)d_in[7];
    float* out = (float*)d_out;

    int n = in_sizes[0] / FDIM;
    int e = in_sizes[5];

    k_init<<<(n + 255) / 256, 256>>>(n);
    k_feats<<<((size_t)n * 32 + 255) / 256, 256>>>(x, a, n);
    k_edge1<<<(e + 255) / 256, 256>>>(row, col, e);

    int nb = (n + 1023) / 1024;
    k_scan1<<<nb, 1024>>>(n);
    k_scan2<<<1, 1>>>(nb, n);
    k_scan3<<<nb, 1024>>>(n);

    k_scatter<<<(e + 255) / 256, 256>>>(row, col, adj, e);

    int spmm_blocks = (n + 7) / 8;
    for (int step = 0; step < 3; step++)
        k_spmm<<<spmm_blocks, 256>>>(x, out, cheb, step, n);
}

// round 7
// speedup vs baseline: 2.2407x; 1.1401x over previous
#include <cuda_runtime.h>
#include <cuda_fp16.h>
#include <cstddef>

#define NMAX 100000
#define EMAX 1600000
#define FDIM 128

// ---------------- static scratch (no allocs allowed) ----------------
__device__ float    g_s[NMAX];            // row exp-sum (unnormalized)
__device__ float    g_rowsum[NMAX];       // rowsum of adj .* P (normalized at scatter)
__device__ int      g_count[NMAX];        // row degree
__device__ int      g_off[NMAX + 1];      // CSR offsets
__device__ int      g_bsum[1024];         // scan block sums
__device__ float    g_feat1[NMAX];
__device__ float    g_feat2[NMAX];
__device__ float    g_ev[EMAX];           // exp(leaky(e)) per edge (COO order)
__device__ unsigned short g_rank[EMAX];   // within-row rank of each edge
__device__ int2     g_cu[EMAX];           // CSR interleaved (col, u-bits)
__device__ __half   g_xh[(size_t)NMAX * FDIM];   // fp16 copy of x
__device__ __half   g_hA[(size_t)NMAX * FDIM];   // fp16 update hop1
__device__ __half   g_hB[(size_t)NMAX * FDIM];   // fp16 update hop2

// ---------------- kernels ----------------

// feat1/feat2 dot products + fused x->fp16 conversion + per-row state init.
// One warp per node, float4 lanes.
__global__ void k_feats(const float* __restrict__ x, const float* __restrict__ a, int n) {
    int gw = (blockIdx.x * blockDim.x + threadIdx.x) >> 5;
    int lane = threadIdx.x & 31;
    if (gw >= n) return;
    float4 v  = __ldg((const float4*)(x + (size_t)gw * FDIM) + lane);
    float4 a1 = __ldg((const float4*)a + lane);
    float4 a2 = __ldg((const float4*)(a + FDIM) + lane);

    // fp16 copy of this x row (lane owns features [4*lane, 4*lane+4))
    __half2 h0 = __floats2half2_rn(v.x, v.y);
    __half2 h1 = __floats2half2_rn(v.z, v.w);
    uint2 packed;
    packed.x = *(unsigned*)&h0;
    packed.y = *(unsigned*)&h1;
    ((uint2*)g_xh)[(size_t)gw * 32 + lane] = packed;

    float d1 = v.x * a1.x + v.y * a1.y + v.z * a1.z + v.w * a1.w;
    float d2 = v.x * a2.x + v.y * a2.y + v.z * a2.z + v.w * a2.w;
    #pragma unroll
    for (int o = 16; o; o >>= 1) {
        d1 += __shfl_down_sync(0xffffffffu, d1, o);
        d2 += __shfl_down_sync(0xffffffffu, d2, o);
    }
    if (lane == 0) {
        g_feat1[gw] = d1; g_feat2[gw] = d2;
        g_s[gw] = 0.f; g_rowsum[gw] = 0.f; g_count[gw] = 0;
    }
}

// single edge pass: exp(leaky(e)) (no max-shift), row sum, degree + rank
__global__ void k_edge1(const int* __restrict__ row, const int* __restrict__ col, int e) {
    int j = blockIdx.x * blockDim.x + threadIdx.x;
    if (j >= e) return;
    int r = row[j];
    float ev = __ldg(&g_feat1[r]) + __ldg(&g_feat2[col[j]]);
    ev = (ev >= 0.f) ? ev : 0.2f * ev;
    float ex = __expf(ev);
    g_ev[j] = ex;
    atomicAdd(&g_s[r], ex);
    int rank = atomicAdd(&g_count[r], 1);
    g_rank[j] = (unsigned short)rank;
}

// scan 1: per-1024-block exclusive scan of degrees; block totals in g_bsum
__global__ void k_scan1(int n) {
    __shared__ int sh[1024];
    int i = blockIdx.x * 1024 + threadIdx.x;
    int v = (i < n) ? g_count[i] : 0;
    sh[threadIdx.x] = v;
    __syncthreads();
    #pragma unroll
    for (int o = 1; o < 1024; o <<= 1) {
        int t = (threadIdx.x >= o) ? sh[threadIdx.x - o] : 0;
        __syncthreads();
        sh[threadIdx.x] += t;
        __syncthreads();
    }
    if (i < n) g_off[i] = sh[threadIdx.x] - v;
    if (threadIdx.x == 1023) g_bsum[blockIdx.x] = sh[1023];
}

// scan 2+3 fused: each block warp-scans the (<=1024) block sums before it
__global__ void k_scan23(int nb, int n) {
    __shared__ int s_prefix;
    int b = blockIdx.x;
    if (threadIdx.x < 32) {
        int acc = 0;
        for (int i = threadIdx.x; i < b; i += 32) acc += g_bsum[i];
        #pragma unroll
        for (int o = 16; o; o >>= 1) acc += __shfl_down_sync(0xffffffffu, acc, o);
        if (threadIdx.x == 0) s_prefix = acc;
    }
    __syncthreads();
    int prefix = s_prefix;
    int i = b * 1024 + threadIdx.x;
    if (i < n) g_off[i] += prefix;
    if (b == nb - 1 && threadIdx.x == 0) g_off[n] = prefix + g_bsum[nb - 1];
}

// scatter: normalized u into interleaved CSR, normalized rowsum. No cursor atomic.
__global__ void k_scatter(const int* __restrict__ row, const int* __restrict__ col,
                          const float* __restrict__ adj, int e) {
    int j = blockIdx.x * blockDim.x + threadIdx.x;
    if (j >= e) return;
    int r = row[j];
    float u = g_ev[j] / __ldg(&g_s[r]);       // s>0: row has >=1 edge
    atomicAdd(&g_rowsum[r], 0.5f * adj[j] * u);
    int pos = __ldg(&g_off[r]) + (int)g_rank[j];
    int2 cu;
    cu.x = col[j];
    cu.y = __float_as_int(u);
    g_cu[pos] = cu;
}

// fused SpMM, fp16 gather operands, fp32 accumulation. One WARP per row.
// step 0: hA = U @ xh    step 1: hB = U @ hA
// step 2: acc = U @ hB; out = 0.001 x + w0*hA + w1*hB + w2*acc   (fp32 out)
__global__ void __launch_bounds__(256) k_spmm(const float* __restrict__ x,
                                              float* __restrict__ out,
                                              const float* __restrict__ cheb,
                                              int step, int n) {
    int warp = (blockIdx.x * blockDim.x + threadIdx.x) >> 5;
    int lane = threadIdx.x & 31;
    if (warp >= n) return;
    int r = warp;

    const uint2* in_upd = (const uint2*)((step == 0) ? g_xh : ((step == 1) ? g_hA : g_hB));

    int beg = __ldg(&g_off[r]), end = __ldg(&g_off[r + 1]);

    float4 acc = make_float4(0.f, 0.f, 0.f, 0.f);

    for (int j0 = beg; j0 < end; j0 += 32) {
        int k = j0 + lane;
        int2 cu = make_int2(0, 0);
        if (k < end) cu = __ldg(&g_cu[k]);
        int m = min(32, end - j0);
        #pragma unroll 8
        for (int t = 0; t < m; t++) {
            int   cc = __shfl_sync(0xffffffffu, cu.x, t);
            float uu = __int_as_float(__shfl_sync(0xffffffffu, cu.y, t));
            uint2 raw = __ldg(in_upd + (size_t)cc * 32 + lane);
            float2 f0 = __half22float2(*(__half2*)&raw.x);
            float2 f1 = __half22float2(*(__half2*)&raw.y);
            acc.x += uu * f0.x;
            acc.y += uu * f0.y;
            acc.z += uu * f1.x;
            acc.w += uu * f1.y;
        }
    }

    size_t v2idx = (size_t)r * 32 + lane;
    if (step < 2) {
        __half2 h0 = __floats2half2_rn(acc.x, acc.y);
        __half2 h1 = __floats2half2_rn(acc.z, acc.w);
        uint2 packed;
        packed.x = *(unsigned*)&h0;
        packed.y = *(unsigned*)&h1;
        ((uint2*)(step == 0 ? g_hA : g_hB))[v2idx] = packed;
    } else {
        float rs0 = __ldg(&g_rowsum[r]);
        float c0 = 1.f / (1.f + __expf(-__ldg(&cheb[0])));
        float c1 = 1.f / (1.f + __expf(-__ldg(&cheb[1])));
        float rs1 = rs0 * c0;
        float rs2 = rs1 * c1;
        float w0 = 0.009f * (1.f - 0.9f * rs0);
        float w1 = 0.09f  * (1.f - 0.9f * rs1);
        float w2 = 0.9f   * (1.f - 0.9f * rs2);

        size_t v4idx = (size_t)r * (FDIM / 4) + lane;
        float4 xv = __ldg((const float4*)x + v4idx);
        uint2 rawa = ((const uint2*)g_hA)[v2idx];
        uint2 rawb = ((const uint2*)g_hB)[v2idx];
        float2 a0 = __half22float2(*(__half2*)&rawa.x);
        float2 a1 = __half22float2(*(__half2*)&rawa.y);
        float2 b0 = __half22float2(*(__half2*)&rawb.x);
        float2 b1 = __half22float2(*(__half2*)&rawb.y);
        float4 o;
        o.x = 0.001f * xv.x + w0 * a0.x + w1 * b0.x + w2 * acc.x;
        o.y = 0.001f * xv.y + w0 * a0.y + w1 * b0.y + w2 * acc.y;
        o.z = 0.001f * xv.z + w0 * a1.x + w1 * b1.x + w2 * acc.z;
        o.w = 0.001f * xv.w + w0 * a1.y + w1 * b1.y + w2 * acc.w;
        ((float4*)out)[v4idx] = o;
    }
}

// ---------------- launch ----------------
extern "C" void kernel_launch(void* const* d_in, const int* in_sizes, int n_in,
                              void* d_out, int out_size) {
    const float* x    = (const float*)d_in[0];
    const float* a    = (const float*)d_in[2];
    const float* cheb = (const float*)d_in[4];
    const float* adj  = (const float*)d_in[5];
    const int*   row  = (const int*)d_in[6];
    const int*   col  = (const int*)d_in[7];
    float* out = (float*)d_out;

    int n = in_sizes[0] / FDIM;
    int e = in_sizes[5];

    k_feats<<<((size_t)n * 32 + 255) / 256, 256>>>(x, a, n);
    k_edge1<<<(e + 255) / 256, 256>>>(row, col, e);

    int nb = (n + 1023) / 1024;
    k_scan1<<<nb, 1024>>>(n);
    k_scan23<<<nb, 1024>>>(nb, n);

    k_scatter<<<(e + 255) / 256, 256>>>(row, col, adj, e);

    int spmm_blocks = (n + 7) / 8;
    for (int step = 0; step < 3; step++)
        k_spmm<<<spmm_blocks, 256>>>(x, out, cheb, step, n);
}